// round 17
// baseline (speedup 1.0000x reference)
#include <cuda_runtime.h>
#include <cuda_fp16.h>
#include <cstdint>

// ---------------------------------------------------------------------------
// Problem constants
// ---------------------------------------------------------------------------
#define BATCH  256
#define LIN    2048
#define HNODE  256
#define GLEN   24
#define LOUT   2025
#define TWOH   512
#define KDIM   96
#define NTLOC  8              // tiles of 128 l-positions per CTA (l-half)
#define NQ     2096           // XiQ entries per CTA window

__device__ float g_pp[BATCH * 2 * TWOH];   // per (b, l-half): [max | sum]

// ---------------------------------------------------------------------------
// Helpers
// ---------------------------------------------------------------------------
static __device__ __forceinline__ uint32_t hpack(float a, float b) {
    const unsigned short ha = __half_as_ushort(__float2half(a));
    const unsigned short hb = __half_as_ushort(__float2half(b));
    return (uint32_t)ha | ((uint32_t)hb << 16);
}

// D = A*B + C  (C != D -> accumulators start as bias, no init MOVs)
static __device__ __forceinline__ void mma_f16_c(float* d, const uint32_t* a,
                                                 uint32_t b0, uint32_t b1,
                                                 const float* c) {
    asm volatile(
        "mma.sync.aligned.m16n8k16.row.col.f32.f16.f16.f32 "
        "{%0,%1,%2,%3}, {%4,%5,%6,%7}, {%8,%9}, {%10,%11,%12,%13};"
        : "=f"(d[0]), "=f"(d[1]), "=f"(d[2]), "=f"(d[3])
        : "r"(a[0]), "r"(a[1]), "r"(a[2]), "r"(a[3]), "r"(b0), "r"(b1),
          "f"(c[0]), "f"(c[1]), "f"(c[2]), "f"(c[3]));
}

static __device__ __forceinline__ void mma_f16(float* d, const uint32_t* a,
                                               uint32_t b0, uint32_t b1) {
    asm volatile(
        "mma.sync.aligned.m16n8k16.row.col.f32.f16.f16.f32 "
        "{%0,%1,%2,%3}, {%4,%5,%6,%7}, {%8,%9}, {%0,%1,%2,%3};"
        : "+f"(d[0]), "+f"(d[1]), "+f"(d[2]), "+f"(d[3])
        : "r"(a[0]), "r"(a[1]), "r"(a[2]), "r"(a[3]), "r"(b0), "r"(b1));
}

// ---------------------------------------------------------------------------
// Kernel 1: fully fused implicit-GEMM conv, single-term fp16.
// Prologue builds everything in-CTA: A-fragments from wConv (48 scattered
// LDG, L2-resident) and the XiQ fragment window in smem (never cold, LDS-fed
// mainloop). No prep kernel, no gmem fragment table.
// XiQ entry i (i = 2*(l-L0) + p) = {w(i), w(i+4), w(i+8), w(i+12)} where
// w(2l+p) packs fp16 {x(2p, l), x(2p+1, l)}.
// Grid: 1024 CTAs = (batch, h-half, l-half). 512 threads = 16 warps,
// warp grid 8(M) x 2(N), warp tile 16(h) x 64(l). Per-warp tile stagger.
// ---------------------------------------------------------------------------
__global__ void __launch_bounds__(512, 1)
conv_mma_kernel(const float* __restrict__ x, const float* __restrict__ wConv,
                const float* __restrict__ wRect) {
    __shared__ uint4 XiQ[NQ];              // 33536 B; red overlays after loop

    const int tid   = threadIdx.x;
    const int lane  = tid & 31;
    const int wid   = tid >> 5;
    const int b     = blockIdx.x >> 2;
    const int mh    = (blockIdx.x >> 1) & 1;
    const int lq    = blockIdx.x & 1;
    const int hbase = mh * 128;
    const int L0    = lq * 1024;
    const int wm    = wid & 7;
    const int wn    = wid >> 3;
    const int grp   = lane >> 2;
    const int tg    = lane & 3;
    const int kq    = tg * 2;

    // ---- A fragments: computed in-thread from wConv (issue LDGs first) ----
    float wf[6][4][2];
    {
#pragma unroll
        for (int ks = 0; ks < 6; ++ks)
#pragma unroll
            for (int rr = 0; rr < 4; ++rr) {
                const int r  = wm * 16 + grp + (rr & 1) * 8;
                const int k0 = ks * 16 + kq + (rr >> 1) * 8;    // even
                const int base = (hbase + r) * KDIM + (k0 >> 2);
                wf[ks][rr][0] = wConv[base + (k0 & 3) * GLEN];
                wf[ks][rr][1] = wConv[base + ((k0 & 3) + 1) * GLEN];
            }
    }

    // ---- build XiQ window in smem (overlaps the wConv load latency) ----
    {
        const float* xb = x + (size_t)b * 4 * LIN;
        for (int i = tid; i < NQ; i += 512) {
            const int l = L0 + (i >> 1);
            const int p = i & 1;
            const float* c0p = xb + (size_t)(2 * p) * LIN;
            uint32_t w[4];
#pragma unroll
            for (int j = 0; j < 4; ++j) {
                const int ll = l + 2 * j;
                float c0 = 0.f, c1 = 0.f;
                if (ll < LIN) { c0 = c0p[ll]; c1 = c0p[LIN + ll]; }
                w[j] = hpack(c0, c1);
            }
            uint4 q; q.x = w[0]; q.y = w[1]; q.z = w[2]; q.w = w[3];
            XiQ[i] = q;
        }
    }

    // convert A fragments (wConv values have landed by now)
    uint32_t aH[6][4];
#pragma unroll
    for (int ks = 0; ks < 6; ++ks)
#pragma unroll
        for (int rr = 0; rr < 4; ++rr)
            aH[ks][rr] = hpack(wf[ks][rr][0], wf[ks][rr][1]);

    float rbc[4];                           // bias quad for the C operand
    rbc[0] = wRect[hbase + wm * 16 + grp];
    rbc[1] = rbc[0];
    rbc[2] = wRect[hbase + wm * 16 + 8 + grp];
    rbc[3] = rbc[2];

    __syncthreads();

    const int sbase = 2 * (wn * 64 + grp + (tg >> 1)) + (tg & 1);
    const int toff  = (wid >> 2) << 1;

    float mx[2] = {0.f, 0.f};
    float sm[2] = {0.f, 0.f};

    for (int t = 0; t < NTLOC; ++t) {
        const int ta = (t + toff) & 7;
        const int base_t = sbase + 2 * ta * 128;

        float d[8][4];

        uint4 Q[10];
#pragma unroll
        for (int j = 0; j < 10; ++j)
            Q[j] = XiQ[base_t + 16 * j];

        // even ks = 0: first write per accumulator -> C = bias quad
#pragma unroll
        for (int nt = 0; nt < 8; ++nt)
            mma_f16_c(d[nt], aH[0], Q[nt].x, Q[nt].y, rbc);
#pragma unroll
        for (int kk = 1; kk < 3; ++kk)
#pragma unroll
            for (int nt = 0; nt < 8; ++nt)
                mma_f16(d[nt], aH[2 * kk], Q[nt + kk].x, Q[nt + kk].y);
#pragma unroll
        for (int kk = 0; kk < 3; ++kk)
#pragma unroll
            for (int nt = 0; nt < 8; ++nt)
                mma_f16(d[nt], aH[2 * kk + 1], Q[nt + kk].z, Q[nt + kk].w);

        if (!(lq == 1 && ta == 7)) {
#pragma unroll
            for (int nt = 0; nt < 8; ++nt)
#pragma unroll
                for (int e = 0; e < 4; ++e) {
                    const int rh = e >> 1;
                    mx[rh] = fmaxf(mx[rh], d[nt][e]);       // relu folded in
                    sm[rh] += fmaxf(d[nt][e], 0.f);
                }
        } else {
            const int lb = L0 + ta * 128 + wn * 64;
#pragma unroll
            for (int nt = 0; nt < 8; ++nt)
#pragma unroll
                for (int e = 0; e < 4; ++e) {
                    const int rh = e >> 1;
                    const int n  = lb + nt * 8 + kq + (e & 1);
                    const float r = fmaxf(d[nt][e], 0.f);
                    if (n < LOUT) {
                        mx[rh] = fmaxf(mx[rh], r);
                        sm[rh] += r;
                    }
                }
        }
    }

    // ---- lane-group reduce, cross-wn combine, write partials ----
    __syncthreads();                        // XiQ reads done; overlay scratch
    float* red = (float*)XiQ;
#pragma unroll
    for (int rh = 0; rh < 2; ++rh) {
        float mv = mx[rh], sv = sm[rh];
        mv = fmaxf(mv, __shfl_xor_sync(0xffffffffu, mv, 1));
        sv +=        __shfl_xor_sync(0xffffffffu, sv, 1);
        mv = fmaxf(mv, __shfl_xor_sync(0xffffffffu, mv, 2));
        sv +=        __shfl_xor_sync(0xffffffffu, sv, 2);
        if (tg == 0) {
            const int m = wm * 16 + rh * 8 + grp;
            red[wn * 128 + m]       = mv;
            red[256 + wn * 128 + m] = sv;
        }
    }
    __syncthreads();

    if (tid < 128) {
        const float mv = fmaxf(red[tid], red[128 + tid]);
        const float sv = red[256 + tid] + red[384 + tid];
        float* pp = g_pp + (size_t)(b * 2 + lq) * TWOH;
        pp[hbase + tid]         = mv;
        pp[HNODE + hbase + tid] = sv;      // unscaled sum
    }
}

// ---------------------------------------------------------------------------
// Kernel 2: fused MLP head. 32 CTAs x 512 threads, 8 batches each.
// ---------------------------------------------------------------------------
__global__ void __launch_bounds__(512)
mlp_kernel(const float* __restrict__ wH, const float* __restrict__ wHB,
           const float* __restrict__ wNeu, const float* __restrict__ wNB,
           float* __restrict__ out) {
    __shared__ float4 prow[2][TWOH];
    __shared__ float  redsm[128];

    const int tid = threadIdx.x;
    const int b0  = blockIdx.x * 8;
    const int o   = tid;

    {
        const int i = tid;
        const float inv = 1.0f / LOUT;
#pragma unroll
        for (int h = 0; h < 2; ++h) {
            float4 v;
#pragma unroll
            for (int j = 0; j < 4; ++j) {
                const int bb = b0 + h * 4 + j;
                const float* p0 = g_pp + (size_t)(bb * 2 + 0) * TWOH;
                const float* p1 = g_pp + (size_t)(bb * 2 + 1) * TWOH;
                ((float*)&v)[j] = (i < HNODE) ? fmaxf(p0[i], p1[i])
                                              : (p0[i] + p1[i]) * inv;
            }
            prow[h][i] = v;
        }
    }
    __syncthreads();

    float a[8];
#pragma unroll
    for (int j = 0; j < 8; ++j) a[j] = 0.f;
#pragma unroll 4
    for (int i = 0; i < TWOH; ++i) {
        const float w = wH[i * TWOH + o];
        const float4 p0 = prow[0][i];
        const float4 p1 = prow[1][i];
        a[0] = fmaf(p0.x, w, a[0]);
        a[1] = fmaf(p0.y, w, a[1]);
        a[2] = fmaf(p0.z, w, a[2]);
        a[3] = fmaf(p0.w, w, a[3]);
        a[4] = fmaf(p1.x, w, a[4]);
        a[5] = fmaf(p1.y, w, a[5]);
        a[6] = fmaf(p1.z, w, a[6]);
        a[7] = fmaf(p1.w, w, a[7]);
    }

    const float hb = wHB[o];
    const float wv = wNeu[o];
    const int lane = tid & 31, wid = tid >> 5;
#pragma unroll
    for (int j = 0; j < 8; ++j) {
        float v = fmaxf(a[j] + hb, 0.f) * wv;
        v += __shfl_xor_sync(0xffffffffu, v, 16);
        v += __shfl_xor_sync(0xffffffffu, v, 8);
        v += __shfl_xor_sync(0xffffffffu, v, 4);
        v += __shfl_xor_sync(0xffffffffu, v, 2);
        v += __shfl_xor_sync(0xffffffffu, v, 1);
        if (lane == 0) redsm[j * 16 + wid] = v;
    }
    __syncthreads();

    if (tid < 8) {
        float s = 0.f;
#pragma unroll
        for (int i = 0; i < 16; ++i) s += redsm[tid * 16 + i];
        out[b0 + tid] = 0.5f * s + wNB[0];
    }
}

// ---------------------------------------------------------------------------
// Launch (two kernels total)
// ---------------------------------------------------------------------------
extern "C" void kernel_launch(void* const* d_in, const int* in_sizes, int n_in,
                              void* d_out, int out_size) {
    const float* x     = (const float*)d_in[0];
    const float* wConv = (const float*)d_in[1];
    const float* wRect = (const float*)d_in[2];
    const float* wH    = (const float*)d_in[3];
    const float* wHB   = (const float*)d_in[4];
    const float* wNeu  = (const float*)d_in[5];
    const float* wNB   = (const float*)d_in[6];
    float* out = (float*)d_out;

    conv_mma_kernel<<<BATCH * 4, 512>>>(x, wConv, wRect);
    mlp_kernel<<<32, 512>>>(wH, wHB, wNeu, wNB, out);
}